// round 2
// baseline (speedup 1.0000x reference)
#include <cuda_runtime.h>
#include <cfloat>
#include <cstdint>

// ---------------- problem constants ----------------
#define F_T   8
#define S     24
#define NVID  4608          // F_T*S*S
#define NTOK  4609          // NVID + 1 (bos)
#define HEADS 8
#define DHEAD 64
#define INNER 512
#define NKEY  28            // bos + 27 neighbors
#define KROW  520           // padded smem row stride (floats), 16B aligned, mod32=8

// ---------------- scratch (device globals; no allocs allowed) ----------------
__device__ float g_q [NTOK * INNER];
__device__ float g_k [NTOK * INNER];
__device__ float g_v [NTOK * INNER];
__device__ float g_ao[NTOK * INNER];

// ---------------- 128x128x8 fp32 SGEMM ----------------
// C[M,N] = A[M,K] * B[K,N] (+bias), all row-major. 256 threads, 8x8 per thread
// (split 4+4 rows/cols to reduce smem bank conflicts).
__global__ void __launch_bounds__(256) sgemm128(
    const float* __restrict__ A, const float* __restrict__ B,
    float* __restrict__ C, const float* __restrict__ bias,
    int M, int N, int K, int lda, int ldb, int ldc)
{
    __shared__ float As[8][128];
    __shared__ float Bs[8][128];

    const int bm = blockIdx.y * 128;
    const int bn = blockIdx.x * 128;
    const int tid = threadIdx.x;

    const int arow = tid >> 1;            // 0..127
    const int acol = (tid & 1) * 4;       // 0 or 4
    const int brow = tid >> 5;            // 0..7
    const int bcol = (tid & 31) * 4;      // 0..124

    const int tx = tid & 15;              // col thread
    const int ty = tid >> 4;              // row thread

    float acc[8][8];
    #pragma unroll
    for (int i = 0; i < 8; i++)
        #pragma unroll
        for (int j = 0; j < 8; j++) acc[i][j] = 0.f;

    const bool arow_ok = (bm + arow) < M;
    const float* Aptr = A + (size_t)(bm + arow) * lda + acol;
    const float* Bptr = B + (size_t)brow * ldb + bn + bcol;

    float4 av = arow_ok ? *(const float4*)Aptr : make_float4(0.f,0.f,0.f,0.f);
    float4 bv = *(const float4*)Bptr;

    for (int k0 = 0; k0 < K; k0 += 8) {
        __syncthreads();
        As[acol+0][arow] = av.x;
        As[acol+1][arow] = av.y;
        As[acol+2][arow] = av.z;
        As[acol+3][arow] = av.w;
        *(float4*)&Bs[brow][bcol] = bv;
        __syncthreads();

        if (k0 + 8 < K) {
            Aptr += 8;
            Bptr += (size_t)8 * ldb;
            av = arow_ok ? *(const float4*)Aptr : make_float4(0.f,0.f,0.f,0.f);
            bv = *(const float4*)Bptr;
        }

        #pragma unroll
        for (int kk = 0; kk < 8; kk++) {
            float4 a0 = *(float4*)&As[kk][ty*4];
            float4 a1 = *(float4*)&As[kk][64 + ty*4];
            float4 b0 = *(float4*)&Bs[kk][tx*4];
            float4 b1 = *(float4*)&Bs[kk][64 + tx*4];
            float a[8] = {a0.x,a0.y,a0.z,a0.w, a1.x,a1.y,a1.z,a1.w};
            float b[8] = {b0.x,b0.y,b0.z,b0.w, b1.x,b1.y,b1.z,b1.w};
            #pragma unroll
            for (int i = 0; i < 8; i++)
                #pragma unroll
                for (int j = 0; j < 8; j++)
                    acc[i][j] += a[i] * b[j];
        }
    }

    // epilogue
    float bb[8];
    #pragma unroll
    for (int j = 0; j < 8; j++) {
        int col = bn + ((j < 4) ? (tx*4 + j) : (64 + tx*4 + j - 4));
        bb[j] = bias ? bias[col] : 0.f;
    }
    #pragma unroll
    for (int i = 0; i < 8; i++) {
        int row = bm + ((i < 4) ? (ty*4 + i) : (64 + ty*4 + i - 4));
        if (row < M) {
            float4 o0 = make_float4(acc[i][0]+bb[0], acc[i][1]+bb[1],
                                    acc[i][2]+bb[2], acc[i][3]+bb[3]);
            float4 o1 = make_float4(acc[i][4]+bb[4], acc[i][5]+bb[5],
                                    acc[i][6]+bb[6], acc[i][7]+bb[7]);
            *(float4*)&C[(size_t)row*ldc + bn + tx*4]      = o0;
            *(float4*)&C[(size_t)row*ldc + bn + 64 + tx*4] = o1;
        }
    }
}

// ---------------- attention kernel: 1 CTA per query, 256 threads ----------------
// warp w = head, lane l = key index (l<28).
__global__ void __launch_bounds__(256) attn_kernel(
    const float* __restrict__ gq, const float* __restrict__ gk,
    const float* __restrict__ gv,
    const float* __restrict__ Wth, const float* __restrict__ ax1,
    const float* __restrict__ ax2, const float* __restrict__ ax3,
    float* __restrict__ gao)
{
    extern __shared__ float smf[];
    float* ks = smf;                       // 28*520
    float* vs = ks + NKEY*KROW;            // 28*520
    float* qs = vs + NKEY*KROW;            // 512
    float* pm = qs + 512;                  // 8*32 softmax probs
    float* mx = pm + 256;                  // 8*32 talking-heads-mixed probs
    int*  tok = (int*)(mx + 256);          // 28
    int*  vld = tok + NKEY;                // 28

    const int tid = threadIdx.x;
    const int qi  = blockIdx.x;

    if (qi == NVID) {                      // special block: out row 0 = v_bos
        if (tid < 128)
            *(float4*)(gao + tid*4) = *(const float4*)(gv + tid*4);
        return;
    }

    const int f   = qi / (S*S);
    const int rem = qi - f*(S*S);
    const int r   = rem / S;
    const int c   = rem - r*S;

    if (tid < NKEY) {
        int t, m;
        if (tid == 0) { t = 0; m = 1; }    // bos
        else {
            int off = tid - 1;
            int a = off / 9, r9 = off - a*9, b = r9 / 3, cc = r9 - b*3;
            int fp = f + a - 2, rp = r + b - 2, cp = c + cc - 2;
            m = (fp >= 0) && (rp >= 0) && (cp >= 0);
            t = m ? (1 + fp*(S*S) + rp*S + cp) : 0;
        }
        tok[tid] = t; vld[tid] = m;
    }
    __syncthreads();

    // stage K and V neighbor rows (float4 coalesced loads, conflict-free STS.128)
    #pragma unroll
    for (int it = 0; it < 14; it++) {
        int idx = tid + it*256;            // 0..3583
        int j  = idx >> 7;
        int c4 = (idx & 127) << 2;
        size_t base = (size_t)tok[j]*INNER + c4;
        float4 k4 = *(const float4*)(gk + base);
        float4 v4 = *(const float4*)(gv + base);
        int o = j*KROW + c4;
        *(float4*)(ks + o) = k4;
        *(float4*)(vs + o) = v4;
    }
    if (tid < 128)
        *(float4*)(qs + tid*4) = *(const float4*)(gq + (size_t)(qi+1)*INNER + tid*4);
    __syncthreads();

    const int w = tid >> 5;                // head
    const int l = tid & 31;                // key

    float val = -FLT_MAX;
    int ok = (l < NKEY) ? vld[l] : 0;
    if (l < NKEY) {
        const float* kr = ks + l*KROW + w*DHEAD;
        const float* qr = qs + w*DHEAD;
        float dot = 0.f;
        #pragma unroll
        for (int t = 0; t < DHEAD; t++) {
            int d = (t + l) & 63;          // lane rotation -> conflict-free banks
            dot += qr[d] * kr[d];
        }
        float bias = 0.f;
        if (l >= 1) {
            int off = l - 1;
            int a = off / 9, r9 = off - a*9, b = r9 / 3, cc = r9 - b*3;
            bias = ax1[a*HEADS + w] + ax2[b*HEADS + w] + ax3[cc*HEADS + w];
        }
        val = ok ? (dot * 0.125f + bias) : -FLT_MAX;
    }

    // warp softmax over 28 keys
    float m = val;
    #pragma unroll
    for (int s = 16; s > 0; s >>= 1)
        m = fmaxf(m, __shfl_xor_sync(0xffffffffu, m, s));
    float e = ok ? __expf(val - m) : 0.f;
    float ssum = e;
    #pragma unroll
    for (int s = 16; s > 0; s >>= 1)
        ssum += __shfl_xor_sync(0xffffffffu, ssum, s);
    pm[w*32 + l] = e / ssum;
    __syncthreads();

    // talking heads: mx[h][j] = sum_g Wth[h][g] * p[g][j]
    float mix = 0.f;
    if (l < NKEY) {
        #pragma unroll
        for (int g = 0; g < 8; g++)
            mix += Wth[w*8 + g] * pm[g*32 + l];
    }
    mx[w*32 + l] = (l < NKEY) ? mix : 0.f;
    __syncwarp();

    // AV: lane l covers dims l and l+32 of head w
    float a0 = 0.f, a1 = 0.f;
    #pragma unroll
    for (int j = 0; j < NKEY; j++) {
        float mj = mx[w*32 + j];
        const float* vr = vs + j*KROW + w*DHEAD;
        a0 += mj * vr[l];
        a1 += mj * vr[l + 32];
    }
    size_t ob = (size_t)(qi + 1)*INNER + w*DHEAD;
    gao[ob + l]      = a0;
    gao[ob + l + 32] = a1;
}

// ---------------- launch ----------------
extern "C" void kernel_launch(void* const* d_in, const int* in_sizes, int n_in,
                              void* d_out, int out_size)
{
    const float* x    = (const float*)d_in[0];
    const float* Wq   = (const float*)d_in[1];
    const float* Wkv  = (const float*)d_in[2];
    const float* Wth  = (const float*)d_in[3];
    const float* Wout = (const float*)d_in[4];
    const float* bout = (const float*)d_in[5];
    const float* ax1  = (const float*)d_in[6];
    const float* ax2  = (const float*)d_in[7];
    const float* ax3  = (const float*)d_in[8];
    float* out = (float*)d_out;

    float *q, *k, *v, *ao;
    cudaGetSymbolAddress((void**)&q,  g_q);
    cudaGetSymbolAddress((void**)&k,  g_k);
    cudaGetSymbolAddress((void**)&v,  g_v);
    cudaGetSymbolAddress((void**)&ao, g_ao);

    dim3 blk(256);
    dim3 grd(INNER / 128, (NTOK + 127) / 128);   // (4, 37)

    // QKV projections
    sgemm128<<<grd, blk>>>(x, Wq,        q, nullptr, NTOK, INNER, 512, 512, 512,  512);
    sgemm128<<<grd, blk>>>(x, Wkv,       k, nullptr, NTOK, INNER, 512, 512, 1024, 512);
    sgemm128<<<grd, blk>>>(x, Wkv + 512, v, nullptr, NTOK, INNER, 512, 512, 1024, 512);

    // attention
    size_t smem = (size_t)(2*NKEY*KROW + 512 + 256 + 256 + 64) * sizeof(float);
    cudaFuncSetAttribute(attn_kernel, cudaFuncAttributeMaxDynamicSharedMemorySize, (int)smem);
    attn_kernel<<<NTOK, blk, smem>>>(q, k, v, Wth, ax1, ax2, ax3, ao);

    // output projection + bias
    sgemm128<<<grd, blk>>>(ao, Wout, out, bout, NTOK, INNER, 512, 512, 512, 512);
}

// round 3
// speedup vs baseline: 1.1848x; 1.1848x over previous
#include <cuda_runtime.h>
#include <cfloat>
#include <cstdint>

// ---------------- problem constants ----------------
#define F_T   8
#define S     24
#define NVID  4608          // F_T*S*S
#define NTOK  4609          // NVID + 1 (bos)
#define HEADS 8
#define DHEAD 64
#define INNER 512
#define NKEY  28            // bos + 27 neighbors

// ---------------- scratch (device globals; no allocs allowed) ----------------
__device__ float g_q [NTOK * INNER];
__device__ float g_k [NTOK * INNER];
__device__ float g_v [NTOK * INNER];
__device__ float g_ao[NTOK * INNER];

// ---------------- 128x128x8 fp32 SGEMM ----------------
__global__ void __launch_bounds__(256) sgemm128(
    const float* __restrict__ A, const float* __restrict__ B,
    float* __restrict__ C, const float* __restrict__ bias,
    int M, int N, int K, int lda, int ldb, int ldc)
{
    __shared__ float As[8][128];
    __shared__ float Bs[8][128];

    const int bm = blockIdx.y * 128;
    const int bn = blockIdx.x * 128;
    const int tid = threadIdx.x;

    const int arow = tid >> 1;
    const int acol = (tid & 1) * 4;
    const int brow = tid >> 5;
    const int bcol = (tid & 31) * 4;

    const int tx = tid & 15;
    const int ty = tid >> 4;

    float acc[8][8];
    #pragma unroll
    for (int i = 0; i < 8; i++)
        #pragma unroll
        for (int j = 0; j < 8; j++) acc[i][j] = 0.f;

    const bool arow_ok = (bm + arow) < M;
    const float* Aptr = A + (size_t)(bm + arow) * lda + acol;
    const float* Bptr = B + (size_t)brow * ldb + bn + bcol;

    float4 av = arow_ok ? *(const float4*)Aptr : make_float4(0.f,0.f,0.f,0.f);
    float4 bv = *(const float4*)Bptr;

    for (int k0 = 0; k0 < K; k0 += 8) {
        __syncthreads();
        As[acol+0][arow] = av.x;
        As[acol+1][arow] = av.y;
        As[acol+2][arow] = av.z;
        As[acol+3][arow] = av.w;
        *(float4*)&Bs[brow][bcol] = bv;
        __syncthreads();

        if (k0 + 8 < K) {
            Aptr += 8;
            Bptr += (size_t)8 * ldb;
            av = arow_ok ? *(const float4*)Aptr : make_float4(0.f,0.f,0.f,0.f);
            bv = *(const float4*)Bptr;
        }

        #pragma unroll
        for (int kk = 0; kk < 8; kk++) {
            float4 a0 = *(float4*)&As[kk][ty*4];
            float4 a1 = *(float4*)&As[kk][64 + ty*4];
            float4 b0 = *(float4*)&Bs[kk][tx*4];
            float4 b1 = *(float4*)&Bs[kk][64 + tx*4];
            float a[8] = {a0.x,a0.y,a0.z,a0.w, a1.x,a1.y,a1.z,a1.w};
            float b[8] = {b0.x,b0.y,b0.z,b0.w, b1.x,b1.y,b1.z,b1.w};
            #pragma unroll
            for (int i = 0; i < 8; i++)
                #pragma unroll
                for (int j = 0; j < 8; j++)
                    acc[i][j] += a[i] * b[j];
        }
    }

    float bb[8];
    #pragma unroll
    for (int j = 0; j < 8; j++) {
        int col = bn + ((j < 4) ? (tx*4 + j) : (64 + tx*4 + j - 4));
        bb[j] = bias ? bias[col] : 0.f;
    }
    #pragma unroll
    for (int i = 0; i < 8; i++) {
        int row = bm + ((i < 4) ? (ty*4 + i) : (64 + ty*4 + i - 4));
        if (row < M) {
            float4 o0 = make_float4(acc[i][0]+bb[0], acc[i][1]+bb[1],
                                    acc[i][2]+bb[2], acc[i][3]+bb[3]);
            float4 o1 = make_float4(acc[i][4]+bb[4], acc[i][5]+bb[5],
                                    acc[i][6]+bb[6], acc[i][7]+bb[7]);
            *(float4*)&C[(size_t)row*ldc + bn + tx*4]      = o0;
            *(float4*)&C[(size_t)row*ldc + bn + 64 + tx*4] = o1;
        }
    }
}

// ---------------- attention: 1 CTA/query, warp=head, lane=key, no K/V smem ----
__global__ void __launch_bounds__(256) attn_kernel(
    const float* __restrict__ gq, const float* __restrict__ gk,
    const float* __restrict__ gv,
    const float* __restrict__ Wth, const float* __restrict__ ax1,
    const float* __restrict__ ax2, const float* __restrict__ ax3,
    float* __restrict__ gao)
{
    __shared__ float qs[512];
    __shared__ float pm[8][32];

    const int tid = threadIdx.x;
    const int qi  = blockIdx.x;

    if (qi == NVID) {                      // out row 0 = v_bos
        if (tid < 128)
            *(float4*)(gao + tid*4) = *(const float4*)(gv + tid*4);
        return;
    }

    const int w = tid >> 5;                // head
    const int l = tid & 31;                // key index

    // stage q row (2 KB)
    if (tid < 128)
        *(float4*)(qs + tid*4) = *(const float4*)(gq + (size_t)(qi+1)*INNER + tid*4);

    // per-lane neighbor token index + validity
    const int f   = qi / (S*S);
    const int rem = qi - f*(S*S);
    const int r   = rem / S;
    const int c   = rem - r*S;

    int tok = 0, ok = 0;
    float bias = 0.f;
    if (l == 0) { tok = 0; ok = 1; }
    else if (l < NKEY) {
        int off = l - 1;
        int a = off / 9, r9 = off - a*9, b = r9 / 3, cc = r9 - b*3;
        int fp = f + a - 2, rp = r + b - 2, cp = c + cc - 2;
        ok = (fp >= 0) && (rp >= 0) && (cp >= 0);
        tok = ok ? (1 + fp*(S*S) + rp*S + cp) : 0;
        bias = ax1[a*HEADS + w] + ax2[b*HEADS + w] + ax3[cc*HEADS + w];
    }
    __syncthreads();

    // dot(q_head, k_head[key l]) — K loaded straight to registers, q broadcast
    const float* kr = gk + (size_t)tok*INNER + w*DHEAD;
    const float* qb = qs + w*DHEAD;
    float dot = 0.f;
    #pragma unroll
    for (int h = 0; h < 2; h++) {
        float4 kv[8];
        #pragma unroll
        for (int i = 0; i < 8; i++)
            kv[i] = *(const float4*)(kr + h*32 + i*4);
        #pragma unroll
        for (int i = 0; i < 8; i++) {
            int d = h*32 + i*4;
            dot = fmaf(qb[d+0], kv[i].x, dot);
            dot = fmaf(qb[d+1], kv[i].y, dot);
            dot = fmaf(qb[d+2], kv[i].z, dot);
            dot = fmaf(qb[d+3], kv[i].w, dot);
        }
    }
    float val = ok ? (dot * 0.125f + bias) : -FLT_MAX;

    // warp softmax over 28 keys
    float m = val;
    #pragma unroll
    for (int s = 16; s > 0; s >>= 1)
        m = fmaxf(m, __shfl_xor_sync(0xffffffffu, m, s));
    float e = ok ? __expf(val - m) : 0.f;
    float ssum = e;
    #pragma unroll
    for (int s = 16; s > 0; s >>= 1)
        ssum += __shfl_xor_sync(0xffffffffu, ssum, s);
    pm[w][l] = e / ssum;
    __syncthreads();

    // talking heads: mix_l = sum_g Wth[w][g] * p[g][l]  (per-lane, key l)
    float mix = 0.f;
    if (l < NKEY) {
        #pragma unroll
        for (int g = 0; g < 8; g++)
            mix += Wth[w*8 + g] * pm[g][l];
    }

    // AV: lane l accumulates output dims l and l+32; probs/toks via shuffle
    float a0 = 0.f, a1 = 0.f;
    #pragma unroll
    for (int j = 0; j < NKEY; j++) {
        float mj = __shfl_sync(0xffffffffu, mix, j);
        int   tj = __shfl_sync(0xffffffffu, tok, j);
        const float* vr = gv + (size_t)tj*INNER + w*DHEAD;
        a0 = fmaf(mj, vr[l],      a0);
        a1 = fmaf(mj, vr[l + 32], a1);
    }
    size_t ob = (size_t)(qi + 1)*INNER + w*DHEAD;
    gao[ob + l]      = a0;
    gao[ob + l + 32] = a1;
}

// ---------------- launch ----------------
extern "C" void kernel_launch(void* const* d_in, const int* in_sizes, int n_in,
                              void* d_out, int out_size)
{
    const float* x    = (const float*)d_in[0];
    const float* Wq   = (const float*)d_in[1];
    const float* Wkv  = (const float*)d_in[2];
    const float* Wth  = (const float*)d_in[3];
    const float* Wout = (const float*)d_in[4];
    const float* bout = (const float*)d_in[5];
    const float* ax1  = (const float*)d_in[6];
    const float* ax2  = (const float*)d_in[7];
    const float* ax3  = (const float*)d_in[8];
    float* out = (float*)d_out;

    float *q, *k, *v, *ao;
    cudaGetSymbolAddress((void**)&q,  g_q);
    cudaGetSymbolAddress((void**)&k,  g_k);
    cudaGetSymbolAddress((void**)&v,  g_v);
    cudaGetSymbolAddress((void**)&ao, g_ao);

    dim3 blk(256);
    dim3 grd(INNER / 128, (NTOK + 127) / 128);   // (4, 37)

    sgemm128<<<grd, blk>>>(x, Wq,        q, nullptr, NTOK, INNER, 512, 512, 512,  512);
    sgemm128<<<grd, blk>>>(x, Wkv,       k, nullptr, NTOK, INNER, 512, 512, 1024, 512);
    sgemm128<<<grd, blk>>>(x, Wkv + 512, v, nullptr, NTOK, INNER, 512, 512, 1024, 512);

    attn_kernel<<<NTOK, blk>>>(q, k, v, Wth, ax1, ax2, ax3, ao);

    sgemm128<<<grd, blk>>>(ao, Wout, out, bout, NTOK, INNER, 512, 512, 512, 512);
}

// round 10
// speedup vs baseline: 1.6617x; 1.4025x over previous
#include <cuda_runtime.h>
#include <cfloat>
#include <cstdint>

// ---------------- problem constants ----------------
#define F_T   8
#define S     24
#define NVID  4608
#define NTOK  4609
#define HEADS 8
#define DHEAD 64
#define INNER 512
#define NKEY  28

// ---------------- scratch ----------------
__device__ float g_q  [NTOK * INNER];
__device__ float g_k  [NTOK * INNER];
__device__ float g_v  [NTOK * INNER];
__device__ float g_ao [NTOK * INNER];
__device__ float g_wqt[512 * 512];
__device__ float g_wkt[512 * 512];
__device__ float g_wvt[512 * 512];
__device__ float g_wot[512 * 512];

// ---------------- helpers ----------------
__device__ __forceinline__ uint32_t smem_u32(const void* p) {
    uint32_t a;
    asm("{ .reg .u64 t; cvta.to.shared.u64 t, %1; cvt.u32.u64 %0, t; }" : "=r"(a) : "l"(p));
    return a;
}
__device__ __forceinline__ uint32_t tf32_bits(float f) {
    uint32_t u;
    asm("cvt.rna.tf32.f32 %0, %1;" : "=r"(u) : "f"(f));
    return u;
}
__device__ __forceinline__ void cp16(uint32_t dst, const void* src, bool v) {
    asm volatile("cp.async.ca.shared.global [%0], [%1], 16, %2;"
                 :: "r"(dst), "l"(src), "r"(v ? 16 : 0));
}
#define CP_COMMIT() asm volatile("cp.async.commit_group;" ::: "memory")
#define CP_WAIT1()  asm volatile("cp.async.wait_group 1;" ::: "memory")
#define CP_WAIT0()  asm volatile("cp.async.wait_group 0;" ::: "memory")

__device__ __forceinline__ void mma_tf32(float4& d, const uint32_t* a, const uint32_t* b) {
    asm volatile(
        "mma.sync.aligned.m16n8k8.row.col.f32.tf32.tf32.f32 "
        "{%0,%1,%2,%3}, {%4,%5,%6,%7}, {%8,%9}, {%0,%1,%2,%3};"
        : "+f"(d.x), "+f"(d.y), "+f"(d.z), "+f"(d.w)
        : "r"(a[0]), "r"(a[1]), "r"(a[2]), "r"(a[3]), "r"(b[0]), "r"(b[1]));
}

// ---------------- weight transpose: dst[n][k] = src[k][col0+n] ----------------
__global__ void __launch_bounds__(256) transpose512(
    const float* __restrict__ src, int ld, int col0, float* __restrict__ dst)
{
    __shared__ float t[32][33];
    const int bx = blockIdx.x * 32;
    const int by = blockIdx.y * 32;
    const int x = threadIdx.x, y = threadIdx.y;
    #pragma unroll
    for (int i = 0; i < 32; i += 8)
        t[y + i][x] = src[(size_t)(by + y + i) * ld + col0 + bx + x];
    __syncthreads();
    #pragma unroll
    for (int i = 0; i < 32; i += 8)
        dst[(size_t)(bx + y + i) * 512 + by + x] = t[x][y + i];
}

// ---------------- tf32 mma.sync GEMM: C[M,512] = A[M,512] @ Bt^T (+bias) -----
// 128x128 tile, BK=32, cp.async double buffer, 3-MMA tf32 split.
// smem layout per slot (32KB): A[128][32] then B[128][32], both XOR-swizzled:
// elem (r,k) at float offset r*32 + (k ^ ((r&7)<<2)).
#define GM_SMEM 65536

__global__ void __launch_bounds__(256) mma_gemm(
    const float* __restrict__ A, int M,
    const float* __restrict__ Bt, const float* __restrict__ bias,
    float* __restrict__ C)
{
    extern __shared__ char smem[];
    const uint32_t sbase = smem_u32(smem);
    const int tid = threadIdx.x;
    const int wid = tid >> 5;
    const int lane = tid & 31;
    const int grp = lane >> 2;     // 0..7
    const int tg  = lane & 3;      // 0..3
    const int wm = wid & 1;        // 2 m-halves of 64
    const int wn = wid >> 1;       // 4 n-quarters of 32
    const int bm = blockIdx.y * 128;
    const int bn = blockIdx.x * 128;

    float4 acc[4][4];
    #pragma unroll
    for (int i = 0; i < 4; i++)
        #pragma unroll
        for (int j = 0; j < 4; j++) acc[i][j] = make_float4(0.f, 0.f, 0.f, 0.f);

    // staging addresses (constant per thread)
    const int srow = tid >> 3;            // rows covered: srow, srow+32, +64, +96
    const int sc4  = (tid & 7) * 4;       // float col (4-aligned)

    auto stage = [&](int kb, int slot) {
        const int k0 = kb * 32;
        const uint32_t abase = sbase + slot * 32768u;
        const uint32_t bbase = abase + 16384u;
        #pragma unroll
        for (int j = 0; j < 4; j++) {
            int row = srow + j * 32;
            uint32_t off = (uint32_t)(row * 32 + (sc4 ^ ((row & 7) << 2))) * 4u;
            bool v = (bm + row) < M;
            const float* ag = A + (v ? ((size_t)(bm + row) * 512 + k0 + sc4) : 0);
            cp16(abase + off, ag, v);
            cp16(bbase + off, Bt + (size_t)(bn + row) * 512 + k0 + sc4, true);
        }
        CP_COMMIT();
    };

    stage(0, 0);
    stage(1, 1);

    for (int kb = 0; kb < 16; kb++) {
        if (kb == 15) CP_WAIT0(); else CP_WAIT1();
        __syncthreads();

        const int slot = kb & 1;
        const float* sA = (const float*)(smem + slot * 32768);
        const float* sB = sA + 4096;

        #pragma unroll
        for (int ks = 0; ks < 4; ks++) {
            const int kx0 = (ks * 8 + tg) ^ (grp << 2);
            const int kx1 = kx0 ^ 4;

            uint32_t ah[4][4], al[4][4], bh[4][2], bl[4][2];
            #pragma unroll
            for (int mi = 0; mi < 4; mi++) {
                const float* pa = sA + (wm * 64 + mi * 16 + grp) * 32;
                float x0 = pa[kx0], x1 = pa[256 + kx0];
                float x2 = pa[kx1], x3 = pa[256 + kx1];
                ah[mi][0] = tf32_bits(x0);
                ah[mi][1] = tf32_bits(x1);
                ah[mi][2] = tf32_bits(x2);
                ah[mi][3] = tf32_bits(x3);
                al[mi][0] = __float_as_uint(x0 - __uint_as_float(ah[mi][0]));
                al[mi][1] = __float_as_uint(x1 - __uint_as_float(ah[mi][1]));
                al[mi][2] = __float_as_uint(x2 - __uint_as_float(ah[mi][2]));
                al[mi][3] = __float_as_uint(x3 - __uint_as_float(ah[mi][3]));
            }
            #pragma unroll
            for (int ni = 0; ni < 4; ni++) {
                const float* pb = sB + (wn * 32 + ni * 8 + grp) * 32;
                float y0 = pb[kx0], y1 = pb[kx1];
                bh[ni][0] = tf32_bits(y0);
                bh[ni][1] = tf32_bits(y1);
                bl[ni][0] = __float_as_uint(y0 - __uint_as_float(bh[ni][0]));
                bl[ni][1] = __float_as_uint(y1 - __uint_as_float(bh[ni][1]));
            }
            #pragma unroll
            for (int mi = 0; mi < 4; mi++)
                #pragma unroll
                for (int ni = 0; ni < 4; ni++) {
                    mma_tf32(acc[mi][ni], ah[mi], bh[ni]);
                    mma_tf32(acc[mi][ni], ah[mi], bl[ni]);
                    mma_tf32(acc[mi][ni], al[mi], bh[ni]);
                }
        }
        __syncthreads();
        if (kb + 2 < 16) stage(kb + 2, slot);
    }

    // epilogue
    #pragma unroll
    for (int mi = 0; mi < 4; mi++) {
        const int row0 = bm + wm * 64 + mi * 16 + grp;
        const int row1 = row0 + 8;
        #pragma unroll
        for (int ni = 0; ni < 4; ni++) {
            const int col = bn + wn * 32 + ni * 8 + tg * 2;
            float4 d = acc[mi][ni];
            if (bias) {
                float b0 = bias[col], b1 = bias[col + 1];
                d.x += b0; d.y += b1; d.z += b0; d.w += b1;
            }
            if (row0 < M) *(float2*)(C + (size_t)row0 * 512 + col) = make_float2(d.x, d.y);
            if (row1 < M) *(float2*)(C + (size_t)row1 * 512 + col) = make_float2(d.z, d.w);
        }
    }
}

// ---------------- attention (unchanged, 80us) ----------------
__global__ void __launch_bounds__(256) attn_kernel(
    const float* __restrict__ gq, const float* __restrict__ gk,
    const float* __restrict__ gv,
    const float* __restrict__ Wth, const float* __restrict__ ax1,
    const float* __restrict__ ax2, const float* __restrict__ ax3,
    float* __restrict__ gao)
{
    __shared__ float qs[512];
    __shared__ float pm[8][32];

    const int tid = threadIdx.x;
    const int qi  = blockIdx.x;

    if (qi == NVID) {
        if (tid < 128)
            *(float4*)(gao + tid*4) = *(const float4*)(gv + tid*4);
        return;
    }

    const int w = tid >> 5;
    const int l = tid & 31;

    if (tid < 128)
        *(float4*)(qs + tid*4) = *(const float4*)(gq + (size_t)(qi+1)*INNER + tid*4);

    const int f   = qi / (S*S);
    const int rem = qi - f*(S*S);
    const int r   = rem / S;
    const int c   = rem - r*S;

    int tok = 0, ok = 0;
    float bias = 0.f;
    if (l == 0) { tok = 0; ok = 1; }
    else if (l < NKEY) {
        int off = l - 1;
        int a = off / 9, r9 = off - a*9, b = r9 / 3, cc = r9 - b*3;
        int fp = f + a - 2, rp = r + b - 2, cp = c + cc - 2;
        ok = (fp >= 0) && (rp >= 0) && (cp >= 0);
        tok = ok ? (1 + fp*(S*S) + rp*S + cp) : 0;
        bias = ax1[a*HEADS + w] + ax2[b*HEADS + w] + ax3[cc*HEADS + w];
    }
    __syncthreads();

    const float* kr = gk + (size_t)tok*INNER + w*DHEAD;
    const float* qb = qs + w*DHEAD;
    float dot = 0.f;
    #pragma unroll
    for (int h = 0; h < 2; h++) {
        float4 kv[8];
        #pragma unroll
        for (int i = 0; i < 8; i++)
            kv[i] = *(const float4*)(kr + h*32 + i*4);
        #pragma unroll
        for (int i = 0; i < 8; i++) {
            int d = h*32 + i*4;
            dot = fmaf(qb[d+0], kv[i].x, dot);
            dot = fmaf(qb[d+1], kv[i].y, dot);
            dot = fmaf(qb[d+2], kv[i].z, dot);
            dot = fmaf(qb[d+3], kv[i].w, dot);
        }
    }
    float val = ok ? (dot * 0.125f + bias) : -FLT_MAX;

    float m = val;
    #pragma unroll
    for (int s = 16; s > 0; s >>= 1)
        m = fmaxf(m, __shfl_xor_sync(0xffffffffu, m, s));
    float e = ok ? __expf(val - m) : 0.f;
    float ssum = e;
    #pragma unroll
    for (int s = 16; s > 0; s >>= 1)
        ssum += __shfl_xor_sync(0xffffffffu, ssum, s);
    pm[w][l] = e / ssum;
    __syncthreads();

    float mix = 0.f;
    if (l < NKEY) {
        #pragma unroll
        for (int g = 0; g < 8; g++)
            mix += Wth[w*8 + g] * pm[g][l];
    }

    float a0 = 0.f, a1 = 0.f;
    #pragma unroll
    for (int j = 0; j < NKEY; j++) {
        float mj = __shfl_sync(0xffffffffu, mix, j);
        int   tj = __shfl_sync(0xffffffffu, tok, j);
        const float* vr = gv + (size_t)tj*INNER + w*DHEAD;
        a0 = fmaf(mj, vr[l],      a0);
        a1 = fmaf(mj, vr[l + 32], a1);
    }
    size_t ob = (size_t)(qi + 1)*INNER + w*DHEAD;
    gao[ob + l]      = a0;
    gao[ob + l + 32] = a1;
}

// ---------------- launch ----------------
extern "C" void kernel_launch(void* const* d_in, const int* in_sizes, int n_in,
                              void* d_out, int out_size)
{
    const float* x    = (const float*)d_in[0];
    const float* Wq   = (const float*)d_in[1];
    const float* Wkv  = (const float*)d_in[2];
    const float* Wth  = (const float*)d_in[3];
    const float* Wout = (const float*)d_in[4];
    const float* bout = (const float*)d_in[5];
    const float* ax1  = (const float*)d_in[6];
    const float* ax2  = (const float*)d_in[7];
    const float* ax3  = (const float*)d_in[8];
    float* out = (float*)d_out;

    float *q, *k, *v, *ao, *wqt, *wkt, *wvt, *wot;
    cudaGetSymbolAddress((void**)&q,   g_q);
    cudaGetSymbolAddress((void**)&k,   g_k);
    cudaGetSymbolAddress((void**)&v,   g_v);
    cudaGetSymbolAddress((void**)&ao,  g_ao);
    cudaGetSymbolAddress((void**)&wqt, g_wqt);
    cudaGetSymbolAddress((void**)&wkt, g_wkt);
    cudaGetSymbolAddress((void**)&wvt, g_wvt);
    cudaGetSymbolAddress((void**)&wot, g_wot);

    cudaFuncSetAttribute(mma_gemm, cudaFuncAttributeMaxDynamicSharedMemorySize, GM_SMEM);

    dim3 tblk(32, 8), tgrd(16, 16);
    transpose512<<<tgrd, tblk>>>(Wq,   512,  0,   wqt);
    transpose512<<<tgrd, tblk>>>(Wkv,  1024, 0,   wkt);
    transpose512<<<tgrd, tblk>>>(Wkv,  1024, 512, wvt);
    transpose512<<<tgrd, tblk>>>(Wout, 512,  0,   wot);

    dim3 gblk(256);
    dim3 ggrd(4, 37);   // 148 CTAs = one wave
    mma_gemm<<<ggrd, gblk, GM_SMEM>>>(x, NTOK, wqt, nullptr, q);
    mma_gemm<<<ggrd, gblk, GM_SMEM>>>(x, NTOK, wkt, nullptr, k);
    mma_gemm<<<ggrd, gblk, GM_SMEM>>>(x, NTOK, wvt, nullptr, v);

    attn_kernel<<<NTOK, gblk>>>(q, k, v, Wth, ax1, ax2, ax3, ao);

    mma_gemm<<<ggrd, gblk, GM_SMEM>>>(ao, NTOK, wot, bout, out);
}

// round 15
// speedup vs baseline: 1.8561x; 1.1170x over previous
#include <cuda_runtime.h>
#include <cfloat>
#include <cstdint>

// ---------------- problem constants ----------------
#define F_T   8
#define S     24
#define NVID  4608
#define NTOK  4609
#define HEADS 8
#define DHEAD 64
#define INNER 512
#define NKEY  28

// ---------------- scratch ----------------
__device__ float g_qkv  [NTOK * 1536];     // fused Q|K|V, row stride 1536
__device__ float g_ao   [NTOK * INNER];
__device__ float g_wqkvt[1536 * 512];      // [n][k]: rows 0-511 Wq^T, 512-1023 Wk^T, 1024-1535 Wv^T
__device__ float g_wot  [512 * 512];

// ---------------- helpers ----------------
__device__ __forceinline__ uint32_t smem_u32(const void* p) {
    uint32_t a;
    asm("{ .reg .u64 t; cvta.to.shared.u64 t, %1; cvt.u32.u64 %0, t; }" : "=r"(a) : "l"(p));
    return a;
}
__device__ __forceinline__ uint32_t tf32_bits(float f) {
    uint32_t u;
    asm("cvt.rna.tf32.f32 %0, %1;" : "=r"(u) : "f"(f));
    return u;
}
__device__ __forceinline__ void cp16(uint32_t dst, const void* src, bool v) {
    asm volatile("cp.async.ca.shared.global [%0], [%1], 16, %2;"
                 :: "r"(dst), "l"(src), "r"(v ? 16 : 0));
}
#define CP_COMMIT() asm volatile("cp.async.commit_group;" ::: "memory")
#define CP_WAIT1()  asm volatile("cp.async.wait_group 1;" ::: "memory")
#define CP_WAIT0()  asm volatile("cp.async.wait_group 0;" ::: "memory")

__device__ __forceinline__ void mma_tf32(float4& d, const uint32_t* a, const uint32_t* b) {
    asm volatile(
        "mma.sync.aligned.m16n8k8.row.col.f32.tf32.tf32.f32 "
        "{%0,%1,%2,%3}, {%4,%5,%6,%7}, {%8,%9}, {%0,%1,%2,%3};"
        : "+f"(d.x), "+f"(d.y), "+f"(d.z), "+f"(d.w)
        : "r"(a[0]), "r"(a[1]), "r"(a[2]), "r"(a[3]), "r"(b[0]), "r"(b[1]));
}

// ---------------- fused weight transposes (one launch) ----------------
__global__ void __launch_bounds__(256) transpose_all(
    const float* __restrict__ Wq, const float* __restrict__ Wkv,
    const float* __restrict__ Wout, float* __restrict__ wqkvt,
    float* __restrict__ wot)
{
    __shared__ float t[32][33];
    const float* src; int ld, col0; float* dst;
    switch (blockIdx.z) {
        case 0:  src = Wq;   ld = 512;  col0 = 0;   dst = wqkvt;              break;
        case 1:  src = Wkv;  ld = 1024; col0 = 0;   dst = wqkvt + 512 * 512;  break;
        case 2:  src = Wkv;  ld = 1024; col0 = 512; dst = wqkvt + 1024 * 512; break;
        default: src = Wout; ld = 512;  col0 = 0;   dst = wot;                break;
    }
    const int bx = blockIdx.x * 32;   // n
    const int by = blockIdx.y * 32;   // k
    const int x = threadIdx.x, y = threadIdx.y;
    #pragma unroll
    for (int i = 0; i < 32; i += 8)
        t[y + i][x] = src[(size_t)(by + y + i) * ld + col0 + bx + x];
    __syncthreads();
    #pragma unroll
    for (int i = 0; i < 32; i += 8)
        dst[(size_t)(bx + y + i) * 512 + by + x] = t[x][y + i];
}

// ---------------- tf32 mma.sync GEMM, templated M-tile ----------------
// C[M,N] = A[M,512] @ Bt^T (+bias), Bt[n][k] row-stride 512. n-tile fixed 128.
// MT=128: warp 64x32 (acc[4][4]); MT=64: warp 64x16 (acc[4][2]).
template<int MT>
__global__ void __launch_bounds__(256) mma_gemm(
    const float* __restrict__ A, int M,
    const float* __restrict__ Bt, const float* __restrict__ bias,
    float* __restrict__ C, int N)
{
    constexpr int NI   = (MT == 128) ? 4 : 2;
    constexpr int SLOT = MT * 128 + 16384;   // bytes per slot: A(MT*32f) + B(128*32f)

    extern __shared__ char smem[];
    const uint32_t sbase = smem_u32(smem);
    const int tid = threadIdx.x;
    const int wid = tid >> 5;
    const int lane = tid & 31;
    const int grp = lane >> 2;
    const int tg  = lane & 3;
    const int wm = (MT == 128) ? (wid & 1) : 0;
    const int wn = (MT == 128) ? (wid >> 1) : wid;
    const int bm = blockIdx.y * MT;
    const int bn = blockIdx.x * 128;

    float4 acc[4][NI];
    #pragma unroll
    for (int i = 0; i < 4; i++)
        #pragma unroll
        for (int j = 0; j < NI; j++) acc[i][j] = make_float4(0.f, 0.f, 0.f, 0.f);

    const int srow = tid >> 3;
    const int sc4  = (tid & 7) * 4;

    auto stage = [&](int kb, int slot) {
        const int k0 = kb * 32;
        const uint32_t abase = sbase + (uint32_t)slot * SLOT;
        const uint32_t bbase = abase + (uint32_t)MT * 128;
        #pragma unroll
        for (int j = 0; j < 4; j++) {
            int row = srow + j * 32;
            uint32_t off = (uint32_t)(row * 32 + (sc4 ^ ((row & 7) << 2))) * 4u;
            if (j < MT / 32) {
                bool v = (bm + row) < M;
                const float* ag = A + (v ? ((size_t)(bm + row) * 512 + k0 + sc4) : 0);
                cp16(abase + off, ag, v);
            }
            cp16(bbase + off, Bt + (size_t)(bn + row) * 512 + k0 + sc4, true);
        }
        CP_COMMIT();
    };

    stage(0, 0);
    stage(1, 1);

    for (int kb = 0; kb < 16; kb++) {
        if (kb == 15) CP_WAIT0(); else CP_WAIT1();
        __syncthreads();

        const int slot = kb & 1;
        const float* sA = (const float*)(smem + (size_t)slot * SLOT);
        const float* sB = sA + MT * 32;

        #pragma unroll
        for (int ks = 0; ks < 4; ks++) {
            const int kx0 = (ks * 8 + tg) ^ (grp << 2);
            const int kx1 = kx0 ^ 4;

            uint32_t ah[4][4], al[4][4], bh[NI][2], bl[NI][2];
            #pragma unroll
            for (int mi = 0; mi < 4; mi++) {
                const float* pa = sA + (wm * 64 + mi * 16 + grp) * 32;
                float x0 = pa[kx0], x1 = pa[256 + kx0];
                float x2 = pa[kx1], x3 = pa[256 + kx1];
                ah[mi][0] = tf32_bits(x0);
                ah[mi][1] = tf32_bits(x1);
                ah[mi][2] = tf32_bits(x2);
                ah[mi][3] = tf32_bits(x3);
                al[mi][0] = __float_as_uint(x0 - __uint_as_float(ah[mi][0]));
                al[mi][1] = __float_as_uint(x1 - __uint_as_float(ah[mi][1]));
                al[mi][2] = __float_as_uint(x2 - __uint_as_float(ah[mi][2]));
                al[mi][3] = __float_as_uint(x3 - __uint_as_float(ah[mi][3]));
            }
            #pragma unroll
            for (int ni = 0; ni < NI; ni++) {
                const float* pb = sB + (wn * (NI * 8) + ni * 8 + grp) * 32;
                float y0 = pb[kx0], y1 = pb[kx1];
                bh[ni][0] = tf32_bits(y0);
                bh[ni][1] = tf32_bits(y1);
                bl[ni][0] = __float_as_uint(y0 - __uint_as_float(bh[ni][0]));
                bl[ni][1] = __float_as_uint(y1 - __uint_as_float(bh[ni][1]));
            }
            #pragma unroll
            for (int mi = 0; mi < 4; mi++)
                #pragma unroll
                for (int ni = 0; ni < NI; ni++) {
                    mma_tf32(acc[mi][ni], ah[mi], bh[ni]);
                    mma_tf32(acc[mi][ni], ah[mi], bl[ni]);
                    mma_tf32(acc[mi][ni], al[mi], bh[ni]);
                }
        }
        __syncthreads();
        if (kb + 2 < 16) stage(kb + 2, slot);
    }

    #pragma unroll
    for (int mi = 0; mi < 4; mi++) {
        const int row0 = bm + wm * 64 + mi * 16 + grp;
        const int row1 = row0 + 8;
        #pragma unroll
        for (int ni = 0; ni < NI; ni++) {
            const int col = bn + wn * (NI * 8) + ni * 8 + tg * 2;
            float4 d = acc[mi][ni];
            if (bias) {
                float b0 = bias[col], b1 = bias[col + 1];
                d.x += b0; d.y += b1; d.z += b0; d.w += b1;
            }
            if (row0 < M) *(float2*)(C + (size_t)row0 * N + col) = make_float2(d.x, d.y);
            if (row1 < M) *(float2*)(C + (size_t)row1 * N + col) = make_float2(d.z, d.w);
        }
    }
}

// ---------------- attention: transposed-QK, coalesced K loads ----------------
// warp = head, lane = key. QK: serial key j, lanes cooperatively load K row
// (float2/lane, coalesced), warp xor-reduce -> val lands on lane j.
__global__ void __launch_bounds__(256) attn_kernel(
    const float* __restrict__ qkv,
    const float* __restrict__ Wth, const float* __restrict__ ax1,
    const float* __restrict__ ax2, const float* __restrict__ ax3,
    float* __restrict__ gao)
{
    __shared__ float pm[8][32];

    const int tid = threadIdx.x;
    const int qi  = blockIdx.x;

    if (qi == NVID) {                      // out row 0 = v_bos
        if (tid < 128)
            *(float4*)(gao + tid*4) = *(const float4*)(qkv + 1024 + tid*4);
        return;
    }

    const int w = tid >> 5;
    const int l = tid & 31;

    const int f   = qi / (S*S);
    const int rem = qi - f*(S*S);
    const int r   = rem / S;
    const int c   = rem - r*S;

    int tok = 0, ok = 0;
    float bias = 0.f;
    if (l == 0) { tok = 0; ok = 1; }
    else if (l < NKEY) {
        int off = l - 1;
        int a = off / 9, r9 = off - a*9, b = r9 / 3, cc = r9 - b*3;
        int fp = f + a - 2, rp = r + b - 2, cp = c + cc - 2;
        ok = (fp >= 0) && (rp >= 0) && (cp >= 0);
        tok = ok ? (1 + fp*(S*S) + rp*S + cp) : 0;
        bias = ax1[a*HEADS + w] + ax2[b*HEADS + w] + ax3[cc*HEADS + w];
    }

    // q slice for this head, pre-scaled; lane holds dims 2l, 2l+1
    float2 qv = *(const float2*)(qkv + (size_t)(qi+1)*1536 + w*DHEAD + 2*l);
    qv.x *= 0.125f; qv.y *= 0.125f;

    float val = -FLT_MAX;
    #pragma unroll
    for (int g = 0; g < 2; g++) {
        float2 kd[14];
        int tj[14];
        #pragma unroll
        for (int jj = 0; jj < 14; jj++) {
            tj[jj] = __shfl_sync(0xffffffffu, tok, g*14 + jj);
            kd[jj] = *(const float2*)(qkv + (size_t)tj[jj]*1536 + 512 + w*DHEAD + 2*l);
        }
        #pragma unroll
        for (int jj = 0; jj < 14; jj++) {
            float p = kd[jj].x*qv.x + kd[jj].y*qv.y;
            #pragma unroll
            for (int s = 16; s > 0; s >>= 1)
                p += __shfl_xor_sync(0xffffffffu, p, s);
            if (l == g*14 + jj) val = ok ? (p + bias) : -FLT_MAX;
        }
    }

    // warp softmax over 28 keys
    float m = val;
    #pragma unroll
    for (int s = 16; s > 0; s >>= 1)
        m = fmaxf(m, __shfl_xor_sync(0xffffffffu, m, s));
    int act = (l < NKEY) ? ok : 0;
    float e = act ? __expf(val - m) : 0.f;
    float ssum = e;
    #pragma unroll
    for (int s = 16; s > 0; s >>= 1)
        ssum += __shfl_xor_sync(0xffffffffu, ssum, s);
    pm[w][l] = e / ssum;
    __syncthreads();

    // talking heads
    float mix = 0.f;
    if (l < NKEY) {
        #pragma unroll
        for (int g = 0; g < 8; g++)
            mix += Wth[w*8 + g] * pm[g][l];
    }

    // AV (coalesced per row)
    float a0 = 0.f, a1 = 0.f;
    #pragma unroll
    for (int j = 0; j < NKEY; j++) {
        float mj = __shfl_sync(0xffffffffu, mix, j);
        int   t  = __shfl_sync(0xffffffffu, tok, j);
        const float* vr = qkv + (size_t)t*1536 + 1024 + w*DHEAD;
        a0 = fmaf(mj, vr[l],      a0);
        a1 = fmaf(mj, vr[l + 32], a1);
    }
    size_t ob = (size_t)(qi + 1)*INNER + w*DHEAD;
    gao[ob + l]      = a0;
    gao[ob + l + 32] = a1;
}

// ---------------- launch ----------------
extern "C" void kernel_launch(void* const* d_in, const int* in_sizes, int n_in,
                              void* d_out, int out_size)
{
    const float* x    = (const float*)d_in[0];
    const float* Wq   = (const float*)d_in[1];
    const float* Wkv  = (const float*)d_in[2];
    const float* Wth  = (const float*)d_in[3];
    const float* Wout = (const float*)d_in[4];
    const float* bout = (const float*)d_in[5];
    const float* ax1  = (const float*)d_in[6];
    const float* ax2  = (const float*)d_in[7];
    const float* ax3  = (const float*)d_in[8];
    float* out = (float*)d_out;

    float *qkv, *ao, *wqkvt, *wot;
    cudaGetSymbolAddress((void**)&qkv,   g_qkv);
    cudaGetSymbolAddress((void**)&ao,    g_ao);
    cudaGetSymbolAddress((void**)&wqkvt, g_wqkvt);
    cudaGetSymbolAddress((void**)&wot,   g_wot);

    cudaFuncSetAttribute(mma_gemm<128>, cudaFuncAttributeMaxDynamicSharedMemorySize, 65536);
    cudaFuncSetAttribute(mma_gemm<64>,  cudaFuncAttributeMaxDynamicSharedMemorySize, 49152);

    // weight transposes (one launch)
    transpose_all<<<dim3(16, 16, 4), dim3(32, 8)>>>(Wq, Wkv, Wout, wqkvt, wot);

    // fused QKV GEMM: [4609,512] @ [512,1536] -> qkv (444 CTAs, 3/SM)
    mma_gemm<128><<<dim3(12, 37), 256, 65536>>>(x, NTOK, wqkvt, nullptr, qkv, 1536);

    // attention
    attn_kernel<<<NTOK, 256>>>(qkv, Wth, ax1, ax2, ax3, ao);

    // output projection: 64-row tiles (292 CTAs, 2/SM)
    mma_gemm<64><<<dim3(4, 73), 256, 49152>>>(ao, NTOK, wot, bout, out, 512);
}